// round 2
// baseline (speedup 1.0000x reference)
#include <cuda_runtime.h>

#define N_POS 8192
#define N_NEG 4000
#define N_TOT (N_POS + N_POS * N_NEG)   // 32,776,192 = 8192*4001

// Scratch (no allocations allowed): pos values + per-positive ranks.
__device__ float        g_pos[N_POS];
__device__ unsigned int g_rank[N_POS];

constexpr int TPB = 256;
constexpr int EPT = 4;                       // elements per thread
constexpr int NBLK = N_TOT / (TPB * EPT);    // 32008, exact division

// Pass 1: scan index only (131MB int32). Scatter the 8192 positive values.
// Block 0 also zeroes g_rank for this call (kernel boundary orders it
// before pass 2).
__global__ __launch_bounds__(TPB) void k_scatter_pos(
    const int*   __restrict__ idx,
    const float* __restrict__ pv)
{
    unsigned int base = (blockIdx.x * TPB + threadIdx.x) * EPT;
    int4 a = *reinterpret_cast<const int4*>(idx + base);
    int js[4] = {a.x, a.y, a.z, a.w};
#pragma unroll
    for (int k = 0; k < 4; k++) {
        unsigned int j = (unsigned int)js[k];
        if (j < N_POS) {
            g_pos[j] = pv[base + k];   // rare: 8192 of 32.7M
        }
    }
    if (blockIdx.x == 0) {
        for (int r = threadIdx.x; r < N_POS; r += TPB) g_rank[r] = 0u;
    }
}

// Pass 2: scan index + predict_val (262MB). For negatives, compare against
// the L1-resident 32KB g_pos table and count via reduction atomics.
__global__ __launch_bounds__(TPB) void k_count(
    const int*   __restrict__ idx,
    const float* __restrict__ pv)
{
    unsigned int base = (blockIdx.x * TPB + threadIdx.x) * EPT;
    int4   a = *reinterpret_cast<const int4*>(idx + base);
    float4 v = *reinterpret_cast<const float4*>(pv + base);

    int   js[4] = {a.x, a.y, a.z, a.w};
    float vs[4] = {v.x, v.y, v.z, v.w};
#pragma unroll
    for (int k = 0; k < 4; k++) {
        unsigned int j = (unsigned int)js[k];
        if (j >= N_POS) {
            unsigned int p = (j - N_POS) / N_NEG;  // const-div -> umulhi
            if (vs[k] > g_pos[p]) {
                atomicAdd(&g_rank[p], 1u);         // REDG (no return)
            }
        }
    }
}

// Finalize: one block computes sample_mrr and the mean. All state derived
// fresh from g_rank -> deterministic across graph replays.
__global__ __launch_bounds__(TPB) void k_finalize(float* __restrict__ out)
{
    __shared__ float ssum[TPB];
    float s = 0.0f;
    for (int p = threadIdx.x; p < N_POS; p += TPB) {
        float smrr = 1.0f / (float)(1u + g_rank[p]);
        out[1 + p] = smrr;
        s += smrr;
    }
    ssum[threadIdx.x] = s;
    __syncthreads();
    for (int off = TPB / 2; off > 0; off >>= 1) {
        if (threadIdx.x < off) ssum[threadIdx.x] += ssum[threadIdx.x + off];
        __syncthreads();
    }
    if (threadIdx.x == 0) out[0] = ssum[0] / (float)N_POS;
}

extern "C" void kernel_launch(void* const* d_in, const int* in_sizes, int n_in,
                              void* d_out, int out_size)
{
    const float* pv  = (const float*)d_in[0];
    const int*   idx = (const int*)d_in[1];
    float* out = (float*)d_out;
    (void)in_sizes; (void)n_in; (void)out_size;

    k_scatter_pos<<<NBLK, TPB>>>(idx, pv);
    k_count<<<NBLK, TPB>>>(idx, pv);
    k_finalize<<<1, TPB>>>(out);
}

// round 3
// speedup vs baseline: 1.3874x; 1.3874x over previous
#include <cuda_runtime.h>

#define N_POS 8192
#define N_NEG 4000
#define N_TOT (N_POS + N_POS * N_NEG)   // 32,776,192 = 8192*4001
#define NT4   (N_TOT / 4)               // 8,194,048 vec4 tiles

constexpr int TPB  = 256;
constexpr int NB2  = 592;               // pass-2 blocks (4 per SM, 32KB smem each)
constexpr int NRED = 32;                // reduction blocks (8192/256)

// Static scratch (allocations forbidden).
__device__ float        g_pos[N_POS];
__device__ unsigned int g_hist[NB2 * N_POS];   // per-block histograms, 19.4MB
__device__ float        g_psum[NRED];

// ---------------- Pass 1: scan index (131MB), scatter the 8192 pos values ----
constexpr int EPT1  = 8;
constexpr int NBLK1 = N_TOT / (TPB * EPT1);    // 16004, exact

__global__ __launch_bounds__(TPB) void k_scatter_pos(
    const int*   __restrict__ idx,
    const float* __restrict__ pv)
{
    unsigned int base = (blockIdx.x * TPB + threadIdx.x) * EPT1;
    const int4* p4 = reinterpret_cast<const int4*>(idx + base);
    int4 a = p4[0];
    int4 b = p4[1];
    int js[8] = {a.x, a.y, a.z, a.w, b.x, b.y, b.z, b.w};
#pragma unroll
    for (int k = 0; k < 8; k++) {
        unsigned int j = (unsigned int)js[k];
        if (j < N_POS) g_pos[j] = pv[base + k];   // rare: 8192 of 32.7M
    }
}

// ---------------- Pass 2: privatized smem histograms, rarer-side counting ----
// For p with pos[p] > 0  : count (v >  pos[p])   -> rank = 1 + cnt
// For p with pos[p] <= 0 : count (v <= pos[p])   -> rank = 4001 - cnt
__global__ __launch_bounds__(TPB) void k_count(
    const int*   __restrict__ idx,
    const float* __restrict__ pv)
{
    __shared__ unsigned int hist[N_POS];
    for (int i = threadIdx.x; i < N_POS; i += TPB) hist[i] = 0u;
    __syncthreads();

    const int4*   idx4 = reinterpret_cast<const int4*>(idx);
    const float4* pv4  = reinterpret_cast<const float4*>(pv);

    for (unsigned int t = blockIdx.x * TPB + threadIdx.x; t < NT4; t += NB2 * TPB) {
        int4   a = idx4[t];
        float4 v = pv4[t];
        int   js[4] = {a.x, a.y, a.z, a.w};
        float vs[4] = {v.x, v.y, v.z, v.w};
#pragma unroll
        for (int k = 0; k < 4; k++) {
            unsigned int j = (unsigned int)js[k];
            if (j >= N_POS) {
                unsigned int p = (j - N_POS) / N_NEG;   // const-div -> umulhi
                float pos = g_pos[p];                    // L1-resident 32KB
                // increment iff (v > pos) == (pos > 0): the rarer side (~25%)
                if ((vs[k] > pos) == (pos > 0.0f)) {
                    atomicAdd(&hist[p], 1u);             // ATOMS, spread-addr
                }
            }
        }
    }
    __syncthreads();

    unsigned int* row = g_hist + (size_t)blockIdx.x * N_POS;
    for (int i = threadIdx.x; i < N_POS; i += TPB) row[i] = hist[i];  // coalesced
}

// ---------------- Reduce histograms + sample_mrr + block partial sums --------
__global__ __launch_bounds__(TPB) void k_reduce(float* __restrict__ out)
{
    int p = blockIdx.x * TPB + threadIdx.x;   // 32 blocks x 256 = 8192
    unsigned int cnt = 0;
#pragma unroll 4
    for (int b = 0; b < NB2; b++)
        cnt += g_hist[(size_t)b * N_POS + p]; // coalesced row segments

    float pos  = g_pos[p];
    unsigned int rank = (pos > 0.0f) ? (1u + cnt) : (unsigned int)(N_NEG + 1) - cnt;
    float smrr = 1.0f / (float)rank;
    out[1 + p] = smrr;

    __shared__ float ssum[TPB];
    ssum[threadIdx.x] = smrr;
    __syncthreads();
    for (int off = TPB / 2; off > 0; off >>= 1) {
        if (threadIdx.x < off) ssum[threadIdx.x] += ssum[threadIdx.x + off];
        __syncthreads();
    }
    if (threadIdx.x == 0) g_psum[blockIdx.x] = ssum[0];
}

// ---------------- Deterministic mean -----------------------------------------
__global__ void k_mean(float* __restrict__ out)
{
    if (threadIdx.x == 0) {
        float s = 0.0f;
        for (int i = 0; i < NRED; i++) s += g_psum[i];
        out[0] = s / (float)N_POS;
    }
}

extern "C" void kernel_launch(void* const* d_in, const int* in_sizes, int n_in,
                              void* d_out, int out_size)
{
    const float* pv  = (const float*)d_in[0];
    const int*   idx = (const int*)d_in[1];
    float* out = (float*)d_out;
    (void)in_sizes; (void)n_in; (void)out_size;

    k_scatter_pos<<<NBLK1, TPB>>>(idx, pv);
    k_count<<<NB2, TPB>>>(idx, pv);
    k_reduce<<<NRED, TPB>>>(out);
    k_mean<<<1, 32>>>(out);
}

// round 4
// speedup vs baseline: 3.8016x; 2.7401x over previous
#include <cuda_runtime.h>

#define N_POS 8192
#define N_NEG 4000
#define N_TOT (N_POS + N_POS * N_NEG)   // 32,776,192 = 8192*4001
#define NT4   (N_TOT / 4)               // 8,194,048 vec4 tiles

constexpr int TPB2 = 512;               // pass-2 block size
constexpr int NB2  = 296;               // pass-2 blocks (2 per SM, 64KB smem each)
constexpr int NRED = 32;                // reduction blocks (8192/256)

// Static scratch (allocations forbidden).
__device__ float        g_pos[N_POS];
__device__ unsigned int g_hist[NB2 * N_POS];   // per-block histograms, 9.7MB
__device__ float        g_psum[NRED];

// ---------------- Pass 1: scan index (131MB), scatter the 8192 pos values ----
constexpr int TPB1  = 256;
constexpr int EPT1  = 16;
constexpr int NBLK1 = N_TOT / (TPB1 * EPT1);   // 8002, exact

__global__ __launch_bounds__(TPB1) void k_scatter_pos(
    const int*   __restrict__ idx,
    const float* __restrict__ pv)
{
    unsigned int base = (blockIdx.x * TPB1 + threadIdx.x) * EPT1;
    const int4* p4 = reinterpret_cast<const int4*>(idx + base);
    int4 r[4];
#pragma unroll
    for (int q = 0; q < 4; q++) r[q] = p4[q];
#pragma unroll
    for (int q = 0; q < 4; q++) {
        int js[4] = {r[q].x, r[q].y, r[q].z, r[q].w};
#pragma unroll
        for (int k = 0; k < 4; k++) {
            unsigned int j = (unsigned int)js[k];
            if (j < N_POS) g_pos[j] = pv[base + q * 4 + k];  // rare
        }
    }
}

// ---------------- Pass 2: smem pos table + smem histograms -------------------
// Rarer-side counting: for p with pos[p] > 0 count (v > pos)  -> rank = 1+cnt
//                      for p with pos[p] <= 0 count (v <= pos)-> rank = 4001-cnt
__global__ __launch_bounds__(TPB2) void k_count(
    const int*   __restrict__ idx,
    const float* __restrict__ pv)
{
    __shared__ float        spos[N_POS];   // 32KB
    __shared__ unsigned int hist[N_POS];   // 32KB

    for (int i = threadIdx.x; i < N_POS; i += TPB2) {
        spos[i] = g_pos[i];                // coalesced load of the table
        hist[i] = 0u;
    }
    __syncthreads();

    const int4*   idx4 = reinterpret_cast<const int4*>(idx);
    const float4* pv4  = reinterpret_cast<const float4*>(pv);

    for (unsigned int t = blockIdx.x * TPB2 + threadIdx.x; t < NT4; t += NB2 * TPB2) {
        int4   a = idx4[t];
        float4 v = pv4[t];
        int   js[4] = {a.x, a.y, a.z, a.w};
        float vs[4] = {v.x, v.y, v.z, v.w};
#pragma unroll
        for (int k = 0; k < 4; k++) {
            unsigned int j = (unsigned int)js[k];
            if (j >= N_POS) {
                unsigned int p = (j - N_POS) / N_NEG;   // const-div -> umulhi
                float pos = spos[p];                     // LDS, ~4cyc conflicts
                if ((vs[k] > pos) == (pos > 0.0f)) {     // rarer side (~25%)
                    atomicAdd(&hist[p], 1u);             // ATOMS, spread-addr
                }
            }
        }
    }
    __syncthreads();

    unsigned int* row = g_hist + (size_t)blockIdx.x * N_POS;
    for (int i = threadIdx.x; i < N_POS; i += TPB2) row[i] = hist[i];  // coalesced
}

// ---------------- Reduce histograms + sample_mrr + block partial sums --------
__global__ __launch_bounds__(256) void k_reduce(float* __restrict__ out)
{
    int p = blockIdx.x * 256 + threadIdx.x;   // 32 blocks x 256 = 8192
    unsigned int cnt = 0;
#pragma unroll 4
    for (int b = 0; b < NB2; b++)
        cnt += g_hist[(size_t)b * N_POS + p]; // coalesced row segments

    float pos  = g_pos[p];
    unsigned int rank = (pos > 0.0f) ? (1u + cnt) : (unsigned int)(N_NEG + 1) - cnt;
    float smrr = 1.0f / (float)rank;
    out[1 + p] = smrr;

    __shared__ float ssum[256];
    ssum[threadIdx.x] = smrr;
    __syncthreads();
    for (int off = 128; off > 0; off >>= 1) {
        if (threadIdx.x < off) ssum[threadIdx.x] += ssum[threadIdx.x + off];
        __syncthreads();
    }
    if (threadIdx.x == 0) g_psum[blockIdx.x] = ssum[0];
}

// ---------------- Deterministic mean -----------------------------------------
__global__ void k_mean(float* __restrict__ out)
{
    if (threadIdx.x == 0) {
        float s = 0.0f;
        for (int i = 0; i < NRED; i++) s += g_psum[i];
        out[0] = s / (float)N_POS;
    }
}

extern "C" void kernel_launch(void* const* d_in, const int* in_sizes, int n_in,
                              void* d_out, int out_size)
{
    const float* pv  = (const float*)d_in[0];
    const int*   idx = (const int*)d_in[1];
    float* out = (float*)d_out;
    (void)in_sizes; (void)n_in; (void)out_size;

    k_scatter_pos<<<NBLK1, TPB1>>>(idx, pv);
    k_count<<<NB2, TPB2>>>(idx, pv);
    k_reduce<<<NRED, 256>>>(out);
    k_mean<<<1, 32>>>(out);
}